// round 13
// baseline (speedup 1.0000x reference)
#include <cuda_runtime.h>
#include <math.h>

#define IMG 224
#define NB 128
#define NPTS 16384
#define PLANE (IMG*IMG)          // 50176
#define PLANE4 (PLANE/4)         // 12544

#define PREP_BLOCKS 2048         // 16 per batch
#define ZCHUNK 784               // NB*PLANE4 / PREP_BLOCKS float4s per block

// Order-preserving float<->uint encoding. Identity for atomicMax is 0.
__device__ __forceinline__ unsigned fenc(float f) {
    unsigned u = __float_as_uint(f);
    return (u >> 31) ? ~u : (u | 0x80000000u);
}
__device__ __forceinline__ float fdec(unsigned u) {
    return (u >> 31) ? __uint_as_float(u & 0x7FFFFFFFu) : __uint_as_float(~u);
}

// zmin/zmax encodings: atomicMax-idempotent across graph replays.
__device__ unsigned g_zmax_enc[NB];
__device__ unsigned g_zminc[NB];

// 8B / 16B vector float add-reductions to global (sm_90+).
__device__ __forceinline__ void red2(float* p, float a, float b) {
    asm volatile("red.global.add.v2.f32 [%0], {%1, %2};"
                 :: "l"(p), "f"(a), "f"(b) : "memory");
}
__device__ __forceinline__ void red4(float* p, float a, float b, float c, float d) {
    asm volatile("red.global.add.v4.f32 [%0], {%1, %2, %3, %4};"
                 :: "l"(p), "f"(a), "f"(b), "f"(c), "f"(d) : "memory");
}

// ---------------------------------------------------------------------------
// Kernel 1: fused prep, 2048 blocks (16/batch). Each block zeroes 784 float4
// of ch0 (stores first, fire-and-forget) and reduces 256 point-groups.
// ---------------------------------------------------------------------------
__global__ void __launch_bounds__(256) k_prep(const float* __restrict__ pts,
                                              const float* __restrict__ az,
                                              const float* __restrict__ el,
                                              float4* __restrict__ out4) {
    int blk = blockIdx.x;
    int b = blk >> 4, sub = blk & 15;

    // ---- zero stores first (no dependencies, never stall) ----
    {
        float4 z = make_float4(0.f, 0.f, 0.f, 0.f);
        int base = blk * ZCHUNK + threadIdx.x;
        #pragma unroll
        for (int j = 0; j < 4; j++) {
            int f = base + j * 256;              // flat ch0-float4 index
            if (j < 3 || f < (blk + 1) * ZCHUNK) {
                int fb = f / PLANE4;
                out4[(size_t)f + (size_t)2 * fb * PLANE4] = z;
            }
        }
    }

    // ---- z min/max over this block's 256 point-groups (1 per thread) ----
    float a = az[b], e = el[b];
    float sa = sinf(a), ca = cosf(a);
    float se = sinf(e), ce = cosf(e);
    float r20 = -ce * sa, r21 = se, r22 = ce * ca;

    const float4* p4 = reinterpret_cast<const float4*>(pts + (size_t)b * NPTS * 3);
    int g = sub * 256 + threadIdx.x;
    float4 f0 = p4[3*g + 0];
    float4 f1 = p4[3*g + 1];
    float4 f2 = p4[3*g + 2];
    float z0 = r20*f0.x + r21*f0.y + r22*f0.z;
    float z1 = r20*f0.w + r21*f1.x + r22*f1.y;
    float z2 = r20*f1.z + r21*f1.w + r22*f2.x;
    float z3 = r20*f2.y + r21*f2.z + r22*f2.w;
    float zmin = fminf(fminf(z0, z1), fminf(z2, z3));
    float zmax = fmaxf(fmaxf(z0, z1), fmaxf(z2, z3));

    #pragma unroll
    for (int o = 16; o > 0; o >>= 1) {
        zmin = fminf(zmin, __shfl_xor_sync(0xffffffffu, zmin, o));
        zmax = fmaxf(zmax, __shfl_xor_sync(0xffffffffu, zmax, o));
    }
    __shared__ float smin[8], smax[8];
    int w = threadIdx.x >> 5, l = threadIdx.x & 31;
    if (l == 0) { smin[w] = zmin; smax[w] = zmax; }
    __syncthreads();
    if (threadIdx.x == 0) {
        zmin = smin[0]; zmax = smax[0];
        #pragma unroll
        for (int k = 1; k < 8; k++) {
            zmin = fminf(zmin, smin[k]);
            zmax = fmaxf(zmax, smax[k]);
        }
        atomicMax(&g_zmax_enc[b], fenc(zmax));
        atomicMax(&g_zminc[b],   ~fenc(zmin));
    }
}

// ---------------------------------------------------------------------------
// Kernel 2: rotate + bilinear splat (exact R7 version — measured optimum).
// ---------------------------------------------------------------------------
__device__ __forceinline__ void splat_one(float* img, float xr, float yr, float zr,
                                          float zmin, float inv_range) {
    float feat = 0.3f + 0.7f * (zr - zmin) * inv_range;
    float px = fmaf(xr + 1.0f, 0.5f * IMG, -0.5f);
    float py = fmaf(yr + 1.0f, 0.5f * IMG, -0.5f);
    float px1 = floorf(px), py1 = floorf(py);
    if (px1 < 0.f || py1 < 0.f || px1 > (float)(IMG - 2) || py1 > (float)(IMG - 2))
        return;
    float fx = px - px1, fy = py - py1;
    float gx = 1.f - fx, gy = 1.f - fy;
    float wa = gx * gy * feat;
    float wb = fx * gy * feat;
    float wc = gx * fy * feat;
    float wd = fx * fy * feat;
    int xi = (int)px1, yi = (int)py1;
    int base = yi * IMG + xi;
    int m = xi & 3;
    if ((m & 1) == 0) {
        red2(&img[base],       wa, wb);
        red2(&img[base + IMG], wc, wd);
    } else if (m == 1) {
        red4(&img[base - 1],       0.f, wa, wb, 0.f);
        red4(&img[base - 1 + IMG], 0.f, wc, wd, 0.f);
    } else {
        atomicAdd(&img[base],           wa);
        atomicAdd(&img[base + 1],       wb);
        atomicAdd(&img[base + IMG],     wc);
        atomicAdd(&img[base + IMG + 1], wd);
    }
}

__global__ void __launch_bounds__(256) k_splat(const float* __restrict__ pts,
                                               const float* __restrict__ az,
                                               const float* __restrict__ el,
                                               float* __restrict__ out) {
    int b = blockIdx.y;

    int g = blockIdx.x * 256 + threadIdx.x;   // group of 4 points
    const float4* p4 = reinterpret_cast<const float4*>(pts + (size_t)b * NPTS * 3);
    float4 f0 = p4[3*g + 0];
    float4 f1 = p4[3*g + 1];
    float4 f2 = p4[3*g + 2];

    float a = __ldg(&az[b]), e = __ldg(&el[b]);
    float sa = sinf(a), ca = cosf(a);
    float se = sinf(e), ce = cosf(e);
    float r00 = ca,      r01 = 0.f, r02 = sa;
    float r10 = se * sa, r11 = ce,  r12 = -se * ca;
    float r20 = -ce*sa,  r21 = se,  r22 = ce * ca;
    float zmin = fdec(~__ldg(&g_zminc[b]));
    float zmax = fdec(__ldg(&g_zmax_enc[b]));
    float inv_range = 1.0f / (zmax - zmin + 1e-6f);

    float* img = out + (size_t)b * 3 * PLANE;

    {
        float x = f0.x, y = f0.y, z = f0.z;
        splat_one(img, r00*x + r01*y + r02*z, r10*x + r11*y + r12*z,
                  r20*x + r21*y + r22*z, zmin, inv_range);
    }
    {
        float x = f0.w, y = f1.x, z = f1.y;
        splat_one(img, r00*x + r01*y + r02*z, r10*x + r11*y + r12*z,
                  r20*x + r21*y + r22*z, zmin, inv_range);
    }
    {
        float x = f1.z, y = f1.w, z = f2.x;
        splat_one(img, r00*x + r01*y + r02*z, r10*x + r11*y + r12*z,
                  r20*x + r21*y + r22*z, zmin, inv_range);
    }
    {
        float x = f2.y, y = f2.z, z = f2.w;
        splat_one(img, r00*x + r01*y + r02*z, r10*x + r11*y + r12*z,
                  r20*x + r21*y + r22*z, zmin, inv_range);
    }
}

// ---------------------------------------------------------------------------
// Kernel 3: broadcast ch0 -> ch1, ch2 (exact R7 version — measured optimum).
// ---------------------------------------------------------------------------
__global__ void __launch_bounds__(256) k_bcast(float4* __restrict__ out4) {
    int r0 = blockIdx.x * 256 + threadIdx.x;
    int b = blockIdx.y;
    size_t plane = (size_t)b * 3 * PLANE4;

    float4 v[4];
    int idx[4];
    bool ok[4];
    #pragma unroll
    for (int j = 0; j < 4; j++) {
        idx[j] = r0 + j * 3328;
        ok[j] = idx[j] < PLANE4;
        if (ok[j]) v[j] = out4[plane + idx[j]];
    }
    #pragma unroll
    for (int j = 0; j < 4; j++) {
        if (ok[j]) {
            __stcs(&out4[plane + PLANE4 + idx[j]], v[j]);
            __stcs(&out4[plane + 2 * PLANE4 + idx[j]], v[j]);
        }
    }
}

extern "C" void kernel_launch(void* const* d_in, const int* in_sizes, int n_in,
                              void* d_out, int out_size) {
    const float* pts = (const float*)d_in[0];
    const float* az  = (const float*)d_in[1];
    const float* el  = (const float*)d_in[2];
    float* out = (float*)d_out;

    k_prep<<<PREP_BLOCKS, 256>>>(pts, az, el, (float4*)out);

    dim3 sgrid(16, NB);
    k_splat<<<sgrid, 256>>>(pts, az, el, out);

    dim3 bgrid(13, NB);
    k_bcast<<<bgrid, 256>>>((float4*)out);
}

// round 14
// speedup vs baseline: 1.0287x; 1.0287x over previous
#include <cuda_runtime.h>
#include <math.h>

#define IMG 224
#define NB 128
#define NPTS 16384
#define PLANE (IMG*IMG)          // 50176
#define PLANE4 (PLANE/4)         // 12544

#define PREP_BLOCKS 1024         // 8 per batch
#define ZCHUNK 1568              // NB*PLANE4 / PREP_BLOCKS float4s per block

// Order-preserving float<->uint encoding. Identity for atomicMax is 0.
__device__ __forceinline__ unsigned fenc(float f) {
    unsigned u = __float_as_uint(f);
    return (u >> 31) ? ~u : (u | 0x80000000u);
}
__device__ __forceinline__ float fdec(unsigned u) {
    return (u >> 31) ? __uint_as_float(u & 0x7FFFFFFFu) : __uint_as_float(~u);
}

// zmin/zmax encodings: atomicMax-idempotent across graph replays.
__device__ unsigned g_zmax_enc[NB];
__device__ unsigned g_zminc[NB];

// 8B / 16B vector float add-reductions to global (sm_90+).
__device__ __forceinline__ void red2(float* p, float a, float b) {
    asm volatile("red.global.add.v2.f32 [%0], {%1, %2};"
                 :: "l"(p), "f"(a), "f"(b) : "memory");
}
__device__ __forceinline__ void red4(float* p, float a, float b, float c, float d) {
    asm volatile("red.global.add.v4.f32 [%0], {%1, %2, %3, %4};"
                 :: "l"(p), "f"(a), "f"(b), "f"(c), "f"(d) : "memory");
}

// ---------------------------------------------------------------------------
// Kernel 1: fused prep (R7 structure) with per-warp trig (lane 0 + shfl).
// ---------------------------------------------------------------------------
__global__ void __launch_bounds__(256) k_prep(const float* __restrict__ pts,
                                              const float* __restrict__ az,
                                              const float* __restrict__ el,
                                              float4* __restrict__ out4) {
    int blk = blockIdx.x;
    int b = blk >> 3, sub = blk & 7;

    // ---- zero stores first (no dependencies, never stall) ----
    {
        float4 z = make_float4(0.f, 0.f, 0.f, 0.f);
        int base = blk * ZCHUNK + threadIdx.x;
        #pragma unroll
        for (int j = 0; j < 7; j++) {
            int f = base + j * 256;
            if (j < 6 || f < (blk + 1) * ZCHUNK) {
                int fb = f / PLANE4;
                out4[(size_t)f + (size_t)2 * fb * PLANE4] = z;
            }
        }
    }

    // ---- trig once per warp (lane 0), broadcast via shfl ----
    int l = threadIdx.x & 31;
    float sa, ca, se, ce;
    if (l == 0) {
        float a = __ldg(&az[b]), e = __ldg(&el[b]);
        sa = sinf(a); ca = cosf(a);
        se = sinf(e); ce = cosf(e);
    }
    sa = __shfl_sync(0xffffffffu, sa, 0);
    ca = __shfl_sync(0xffffffffu, ca, 0);
    se = __shfl_sync(0xffffffffu, se, 0);
    ce = __shfl_sync(0xffffffffu, ce, 0);
    float r20 = -ce * sa, r21 = se, r22 = ce * ca;

    // ---- z min/max over this block's slice ----
    const float4* p4 = reinterpret_cast<const float4*>(pts + (size_t)b * NPTS * 3);
    float zmin = 1e30f, zmax = -1e30f;

    #pragma unroll
    for (int j = 0; j < 2; j++) {
        int g = sub * 512 + threadIdx.x + j * 256;
        float4 f0 = p4[3*g + 0];
        float4 f1 = p4[3*g + 1];
        float4 f2 = p4[3*g + 2];
        float z0 = r20*f0.x + r21*f0.y + r22*f0.z;
        float z1 = r20*f0.w + r21*f1.x + r22*f1.y;
        float z2 = r20*f1.z + r21*f1.w + r22*f2.x;
        float z3 = r20*f2.y + r21*f2.z + r22*f2.w;
        zmin = fminf(zmin, fminf(fminf(z0, z1), fminf(z2, z3)));
        zmax = fmaxf(zmax, fmaxf(fmaxf(z0, z1), fmaxf(z2, z3)));
    }

    #pragma unroll
    for (int o = 16; o > 0; o >>= 1) {
        zmin = fminf(zmin, __shfl_xor_sync(0xffffffffu, zmin, o));
        zmax = fmaxf(zmax, __shfl_xor_sync(0xffffffffu, zmax, o));
    }
    __shared__ float smin[8], smax[8];
    int w = threadIdx.x >> 5;
    if (l == 0) { smin[w] = zmin; smax[w] = zmax; }
    __syncthreads();
    if (threadIdx.x == 0) {
        zmin = smin[0]; zmax = smax[0];
        #pragma unroll
        for (int k = 1; k < 8; k++) {
            zmin = fminf(zmin, smin[k]);
            zmax = fmaxf(zmax, smax[k]);
        }
        atomicMax(&g_zmax_enc[b], fenc(zmax));
        atomicMax(&g_zminc[b],   ~fenc(zmin));
    }
}

// ---------------------------------------------------------------------------
// Kernel 2: rotate + bilinear splat (exact R7 version — measured optimum).
// ---------------------------------------------------------------------------
__device__ __forceinline__ void splat_one(float* img, float xr, float yr, float zr,
                                          float zmin, float inv_range) {
    float feat = 0.3f + 0.7f * (zr - zmin) * inv_range;
    float px = fmaf(xr + 1.0f, 0.5f * IMG, -0.5f);
    float py = fmaf(yr + 1.0f, 0.5f * IMG, -0.5f);
    float px1 = floorf(px), py1 = floorf(py);
    if (px1 < 0.f || py1 < 0.f || px1 > (float)(IMG - 2) || py1 > (float)(IMG - 2))
        return;
    float fx = px - px1, fy = py - py1;
    float gx = 1.f - fx, gy = 1.f - fy;
    float wa = gx * gy * feat;
    float wb = fx * gy * feat;
    float wc = gx * fy * feat;
    float wd = fx * fy * feat;
    int xi = (int)px1, yi = (int)py1;
    int base = yi * IMG + xi;
    int m = xi & 3;
    if ((m & 1) == 0) {
        red2(&img[base],       wa, wb);
        red2(&img[base + IMG], wc, wd);
    } else if (m == 1) {
        red4(&img[base - 1],       0.f, wa, wb, 0.f);
        red4(&img[base - 1 + IMG], 0.f, wc, wd, 0.f);
    } else {
        atomicAdd(&img[base],           wa);
        atomicAdd(&img[base + 1],       wb);
        atomicAdd(&img[base + IMG],     wc);
        atomicAdd(&img[base + IMG + 1], wd);
    }
}

__global__ void __launch_bounds__(256) k_splat(const float* __restrict__ pts,
                                               const float* __restrict__ az,
                                               const float* __restrict__ el,
                                               float* __restrict__ out) {
    int b = blockIdx.y;

    int g = blockIdx.x * 256 + threadIdx.x;   // group of 4 points
    const float4* p4 = reinterpret_cast<const float4*>(pts + (size_t)b * NPTS * 3);
    float4 f0 = p4[3*g + 0];
    float4 f1 = p4[3*g + 1];
    float4 f2 = p4[3*g + 2];

    float a = __ldg(&az[b]), e = __ldg(&el[b]);
    float sa = sinf(a), ca = cosf(a);
    float se = sinf(e), ce = cosf(e);
    float r00 = ca,      r01 = 0.f, r02 = sa;
    float r10 = se * sa, r11 = ce,  r12 = -se * ca;
    float r20 = -ce*sa,  r21 = se,  r22 = ce * ca;
    float zmin = fdec(~__ldg(&g_zminc[b]));
    float zmax = fdec(__ldg(&g_zmax_enc[b]));
    float inv_range = 1.0f / (zmax - zmin + 1e-6f);

    float* img = out + (size_t)b * 3 * PLANE;

    {
        float x = f0.x, y = f0.y, z = f0.z;
        splat_one(img, r00*x + r01*y + r02*z, r10*x + r11*y + r12*z,
                  r20*x + r21*y + r22*z, zmin, inv_range);
    }
    {
        float x = f0.w, y = f1.x, z = f1.y;
        splat_one(img, r00*x + r01*y + r02*z, r10*x + r11*y + r12*z,
                  r20*x + r21*y + r22*z, zmin, inv_range);
    }
    {
        float x = f1.z, y = f1.w, z = f2.x;
        splat_one(img, r00*x + r01*y + r02*z, r10*x + r11*y + r12*z,
                  r20*x + r21*y + r22*z, zmin, inv_range);
    }
    {
        float x = f2.y, y = f2.z, z = f2.w;
        splat_one(img, r00*x + r01*y + r02*z, r10*x + r11*y + r12*z,
                  r20*x + r21*y + r22*z, zmin, inv_range);
    }
}

// ---------------------------------------------------------------------------
// Kernel 3: broadcast ch0 -> ch1, ch2 (exact R7 version — measured optimum).
// ---------------------------------------------------------------------------
__global__ void __launch_bounds__(256) k_bcast(float4* __restrict__ out4) {
    int r0 = blockIdx.x * 256 + threadIdx.x;
    int b = blockIdx.y;
    size_t plane = (size_t)b * 3 * PLANE4;

    float4 v[4];
    int idx[4];
    bool ok[4];
    #pragma unroll
    for (int j = 0; j < 4; j++) {
        idx[j] = r0 + j * 3328;
        ok[j] = idx[j] < PLANE4;
        if (ok[j]) v[j] = out4[plane + idx[j]];
    }
    #pragma unroll
    for (int j = 0; j < 4; j++) {
        if (ok[j]) {
            __stcs(&out4[plane + PLANE4 + idx[j]], v[j]);
            __stcs(&out4[plane + 2 * PLANE4 + idx[j]], v[j]);
        }
    }
}

extern "C" void kernel_launch(void* const* d_in, const int* in_sizes, int n_in,
                              void* d_out, int out_size) {
    const float* pts = (const float*)d_in[0];
    const float* az  = (const float*)d_in[1];
    const float* el  = (const float*)d_in[2];
    float* out = (float*)d_out;

    k_prep<<<PREP_BLOCKS, 256>>>(pts, az, el, (float4*)out);

    dim3 sgrid(16, NB);
    k_splat<<<sgrid, 256>>>(pts, az, el, out);

    dim3 bgrid(13, NB);
    k_bcast<<<bgrid, 256>>>((float4*)out);
}